// round 9
// baseline (speedup 1.0000x reference)
#include <cuda_runtime.h>
#include <math.h>
#include <stdint.h>

#define S_LEN   3072
#define HIDDEN  2048
#define HQ      16
#define HK      2
#define D_HEAD  128
#define QCOLS   (HQ * D_HEAD)   // 2048
#define KCOLS   (HK * D_HEAD)   // 256

// ---------------- scratch (device globals: no allocations allowed) ----------
__device__ float g_Q[S_LEN * QCOLS];   // 24 MB
__device__ float g_K[S_LEN * KCOLS];   //  3 MB
__device__ float g_V[S_LEN * KCOLS];   //  3 MB
__device__ float g_A[S_LEN * QCOLS];   // 24 MB (attention output, pre-Wo)

// ============================================================================
// Common TF32 helpers
// ============================================================================
__device__ __forceinline__ uint32_t f2tf32(float f) {
    uint32_t u;
    asm("cvt.rna.tf32.f32 %0, %1;" : "=r"(u) : "f"(f));
    return u;
}
__device__ __forceinline__ uint32_t u2tf32(uint32_t u) {
    uint32_t o;
    asm("cvt.rna.tf32.f32 %0, %1;" : "=r"(o) : "f"(__uint_as_float(u)));
    return o;
}

__device__ __forceinline__ void mma_tf32(float& d0, float& d1, float& d2, float& d3,
                                         uint32_t a0, uint32_t a1, uint32_t a2, uint32_t a3,
                                         uint32_t b0, uint32_t b1) {
    asm volatile(
        "mma.sync.aligned.m16n8k8.row.col.f32.tf32.tf32.f32 "
        "{%0,%1,%2,%3}, {%4,%5,%6,%7}, {%8,%9}, {%0,%1,%2,%3};\n"
        : "+f"(d0), "+f"(d1), "+f"(d2), "+f"(d3)
        : "r"(a0), "r"(a1), "r"(a2), "r"(a3), "r"(b0), "r"(b1));
}

// ============================================================================
// TF32 GEMM with cp.async 2-stage pipeline: C[M,N] = A[M,K] * B[N,K]^T
// BM=BN=128, BK=32, 256 threads (8 warps, 2x4), warp tile 64x32, 2 CTAs/SM.
// Smem (dynamic, 64 KB): [stage 2][A 4096 u32], then [stage 2][B 4096 u32].
// Raw fp32 lands in fragment-permuted layout via 4B cp.async; cvt.rna at
// fragment-load time (numerics identical to the validated R6/R8 GEMM).
// Requires M%128==0, N%128==0, K%32==0.
// ============================================================================
#define SMEM_GEMM (16384 * 4)   // 65536 bytes

__global__ __launch_bounds__(256, 2)
void tf32_gemm_nt(const float* __restrict__ A, const float* __restrict__ B,
                  float* __restrict__ C, int M, int N, int K) {
    extern __shared__ uint32_t smem[];

    const int t    = threadIdx.x;
    const int warp = t >> 5;
    const int lane = t & 31;
    const int bm   = blockIdx.y * 128;
    const int bn   = blockIdx.x * 128;
    const int wm4  = (warp >> 2) * 4;   // warp msub origin (0 or 4)
    const int wn8  = (warp & 3) * 4;    // warp nsub origin (0,4,8,12)

    // ---- load geometry for i=0 (i-th term adds 32 rows / +256 u32) ----
    const int row  = t >> 3;
    const int cpos = t & 7;
    const int kst  = cpos >> 1;
    const int aBase0 = ((kst * 8 + (row >> 4)) * 32 + (row & 7) * 4) * 4
                       + (((row >> 3) & 1) + 2 * (cpos & 1));
    const int bBase0 = ((kst * 16 + (row >> 3)) * 32 + (row & 7) * 4) * 2
                       + (cpos & 1);
    const float* aP = A + (size_t)(bm + row) * K + cpos * 4;
    const float* bP = B + (size_t)(bn + row) * K + cpos * 4;
    const size_t rstride = (size_t)32 * K;   // 32 rows

    uint32_t sbase;
    asm("{ .reg .u64 tt; cvta.to.shared.u64 tt, %1; cvt.u32.u64 %0, tt; }"
        : "=r"(sbase) : "l"(smem));

    const int niter = K >> 5;

    // ---- stage issue: 16 A + 16 B 4-byte cp.asyncs ----
    auto issue = [&](int stage, int k0) {
        uint32_t ad0 = sbase + (uint32_t)(stage * 4096 + aBase0) * 4;
        uint32_t bd0 = sbase + (uint32_t)(8192 + stage * 4096 + bBase0) * 4;
#pragma unroll
        for (int i = 0; i < 4; i++) {
            const float* as = aP + i * rstride + k0;
            const float* bs = bP + i * rstride + k0;
            uint32_t ad = ad0 + i * 1024;   // +256 u32
            uint32_t bd = bd0 + i * 1024;
#pragma unroll
            for (int j = 0; j < 4; j++) {
                asm volatile("cp.async.ca.shared.global [%0], [%1], 4;"
                             :: "r"(ad + j * 16), "l"(as + j));
                asm volatile("cp.async.ca.shared.global [%0], [%1], 4;"
                             :: "r"(bd + j * 8),  "l"(bs + j));
            }
        }
        asm volatile("cp.async.commit_group;");
    };

    float acc[4][4][4];
#pragma unroll
    for (int m = 0; m < 4; m++)
#pragma unroll
        for (int n = 0; n < 4; n++)
#pragma unroll
            for (int r = 0; r < 4; r++) acc[m][n][r] = 0.0f;

    issue(0, 0);   // prologue

    for (int it = 0; it < niter; it++) {
        if (it + 1 < niter) {
            issue((it + 1) & 1, (it + 1) * 32);
            asm volatile("cp.async.wait_group 1;");
        } else {
            asm volatile("cp.async.wait_group 0;");
        }
        __syncthreads();

        const uint32_t* SAs = smem + (it & 1) * 4096;
        const uint32_t* SBs = smem + 8192 + (it & 1) * 4096;

#pragma unroll
        for (int ks = 0; ks < 4; ks++) {
            uint4 af[4];
            uint2 bf[4];
#pragma unroll
            for (int m = 0; m < 4; m++) {
                af[m] = *(const uint4*)&SAs[((ks * 8 + wm4 + m) * 32 + lane) * 4];
                af[m].x = u2tf32(af[m].x); af[m].y = u2tf32(af[m].y);
                af[m].z = u2tf32(af[m].z); af[m].w = u2tf32(af[m].w);
            }
#pragma unroll
            for (int n = 0; n < 4; n++) {
                bf[n] = *(const uint2*)&SBs[((ks * 16 + wn8 + n) * 32 + lane) * 2];
                bf[n].x = u2tf32(bf[n].x); bf[n].y = u2tf32(bf[n].y);
            }
#pragma unroll
            for (int m = 0; m < 4; m++)
#pragma unroll
                for (int n = 0; n < 4; n++)
                    mma_tf32(acc[m][n][0], acc[m][n][1], acc[m][n][2], acc[m][n][3],
                             af[m].x, af[m].y, af[m].z, af[m].w,
                             bf[n].x, bf[n].y);
        }
        __syncthreads();
    }

    // ---- epilogue ----
    const int wm = (warp >> 2) * 64;
    const int wn = (warp & 3) * 32;
    const int lr = lane >> 2;
    const int lc = (lane & 3) * 2;
#pragma unroll
    for (int m = 0; m < 4; m++) {
#pragma unroll
        for (int n = 0; n < 4; n++) {
            int r0 = bm + wm + m * 16 + lr;
            int c0 = bn + wn + n * 8 + lc;
            *(float2*)&C[(size_t)r0 * N + c0] =
                make_float2(acc[m][n][0], acc[m][n][1]);
            *(float2*)&C[(size_t)(r0 + 8) * N + c0] =
                make_float2(acc[m][n][2], acc[m][n][3]);
        }
    }
}

// ============================================================================
// RoPE in-place.
// ============================================================================
__global__ void rope_kernel(float* __restrict__ x, const int* __restrict__ pos,
                            int nheads, int total) {
    int idx = blockIdx.x * blockDim.x + threadIdx.x;
    if (idx >= total) return;
    int fi = idx & 63;
    int h  = (idx >> 6) % nheads;
    int s  = idx / (nheads * 64);

    float p    = (float)pos[s];
    float invf = powf(10000.0f, -((float)fi) / 64.0f);
    float sn, cs;
    sincosf(p * invf, &sn, &cs);

    size_t base = (size_t)s * (nheads * D_HEAD) + h * D_HEAD + fi;
    float x1 = x[base];
    float x2 = x[base + 64];
    x[base]      = x1 * cs - x2 * sn;
    x[base + 64] = x2 * cs + x1 * sn;
}

// ============================================================================
// TF32 tensor-core causal flash attention (validated in R8, unchanged).
// Block = 256 threads (8 warps) x (q-tile 128, head). Warp w owns q-rows
// [w*16, w*16+16). K/V tiles of 64 keys. GQA: q-head h -> kv-head (h & 1).
// ============================================================================
#define SMEM_FA (40960 * 4)

__global__ __launch_bounds__(256, 1)
void flash_tf32(const float* __restrict__ Q, const float* __restrict__ Kb,
                const float* __restrict__ Vb, float* __restrict__ O) {
    extern __shared__ uint32_t sm[];
    uint32_t* Qs = sm;            // 16384
    uint32_t* Ks = sm + 16384;    //  8192
    uint32_t* Vs = sm + 24576;    //  8192
    uint32_t* Ps = sm + 32768;    //  8192

    const int t    = threadIdx.x;
    const int w    = t >> 5;
    const int lane = t & 31;
    const int qt   = gridDim.x - 1 - blockIdx.x;
    const int h    = blockIdx.y;
    const int q0   = qt * 128;
    const int kvoff = (h & 1) * D_HEAD;
    const float SCALE = 0.08838834764831845f;

#pragma unroll
    for (int i = 0; i < 16; i++) {
        int id  = t + i * 256;
        int row = id >> 5;
        int cp  = id & 31;
        float4 qv = *(const float4*)&Q[(size_t)(q0 + row) * QCOLS + h * D_HEAD + cp * 4];
        int msub = row >> 4, m8 = (row >> 3) & 1, rr = row & 7;
        int ks = cp >> 1, c4 = cp & 1;
        int base = ((ks * 8 + msub) * 32 + rr * 4) * 4 + (m8 + 2 * c4);
        Qs[base + 0]  = f2tf32(qv.x * SCALE);
        Qs[base + 4]  = f2tf32(qv.y * SCALE);
        Qs[base + 8]  = f2tf32(qv.z * SCALE);
        Qs[base + 12] = f2tf32(qv.w * SCALE);
    }

    float m_[2] = {-INFINITY, -INFINITY};
    float l_[2] = {0.0f, 0.0f};
    float o_[16][4];
#pragma unroll
    for (int n = 0; n < 16; n++)
#pragma unroll
        for (int r = 0; r < 4; r++) o_[n][r] = 0.0f;

    const int nkt = qt * 2 + 2;
    const int r   = lane >> 2;
    const int c2  = (lane & 3) * 2;
    const int rg0 = q0 + w * 16 + r;
    const int rg1 = rg0 + 8;

    float4 kf[8], vf[8];
#pragma unroll
    for (int i = 0; i < 8; i++) {
        int id = t + i * 256;
        int row = id >> 5, cp = id & 31;
        kf[i] = *(const float4*)&Kb[(size_t)row * KCOLS + kvoff + cp * 4];
        vf[i] = *(const float4*)&Vb[(size_t)row * KCOLS + kvoff + cp * 4];
    }

    for (int kt = 0; kt < nkt; kt++) {
        const int k0 = kt * 64;

#pragma unroll
        for (int i = 0; i < 8; i++) {
            int id = t + i * 256;
            int row = id >> 5, cp = id & 31;
            int ks = cp >> 1, k4 = cp & 1;
            int kb = ((ks * 8 + (row >> 3)) * 32 + (row & 7) * 4) * 2 + k4;
            Ks[kb + 0] = f2tf32(kf[i].x);
            Ks[kb + 2] = f2tf32(kf[i].y);
            Ks[kb + 4] = f2tf32(kf[i].z);
            Ks[kb + 6] = f2tf32(kf[i].w);
            int vks = row >> 3, vk4 = (row & 7) >> 2, vq = row & 3;
            int nsub = cp >> 1, nnb = (cp & 1) * 4;
            int vb = ((vks * 16 + nsub) * 32 + nnb * 4 + vq) * 2 + vk4;
            Vs[vb + 0]  = f2tf32(vf[i].x);
            Vs[vb + 8]  = f2tf32(vf[i].y);
            Vs[vb + 16] = f2tf32(vf[i].z);
            Vs[vb + 24] = f2tf32(vf[i].w);
        }
        __syncthreads();

        if (kt + 1 < nkt) {
            int k0n = (kt + 1) * 64;
#pragma unroll
            for (int i = 0; i < 8; i++) {
                int id = t + i * 256;
                int row = id >> 5, cp = id & 31;
                kf[i] = *(const float4*)&Kb[(size_t)(k0n + row) * KCOLS + kvoff + cp * 4];
                vf[i] = *(const float4*)&Vb[(size_t)(k0n + row) * KCOLS + kvoff + cp * 4];
            }
        }

        float acc[8][4];
#pragma unroll
        for (int n = 0; n < 8; n++)
#pragma unroll
            for (int x = 0; x < 4; x++) acc[n][x] = 0.0f;

#pragma unroll
        for (int ks = 0; ks < 16; ks++) {
            uint4 a = *(const uint4*)&Qs[((ks * 8 + w) * 32 + lane) * 4];
#pragma unroll
            for (int nt = 0; nt < 8; nt++) {
                uint2 b = *(const uint2*)&Ks[((ks * 8 + nt) * 32 + lane) * 2];
                mma_tf32(acc[nt][0], acc[nt][1], acc[nt][2], acc[nt][3],
                         a.x, a.y, a.z, a.w, b.x, b.y);
            }
        }

        if (kt >= nkt - 2) {
#pragma unroll
            for (int nt = 0; nt < 8; nt++) {
                int cg = k0 + nt * 8 + c2;
                if (cg > rg0)     acc[nt][0] = -1e30f;
                if (cg + 1 > rg0) acc[nt][1] = -1e30f;
                if (cg > rg1)     acc[nt][2] = -1e30f;
                if (cg + 1 > rg1) acc[nt][3] = -1e30f;
            }
        }

        float mx0 = -INFINITY, mx1 = -INFINITY;
#pragma unroll
        for (int nt = 0; nt < 8; nt++) {
            mx0 = fmaxf(mx0, fmaxf(acc[nt][0], acc[nt][1]));
            mx1 = fmaxf(mx1, fmaxf(acc[nt][2], acc[nt][3]));
        }
        mx0 = fmaxf(mx0, __shfl_xor_sync(0xffffffffu, mx0, 1));
        mx0 = fmaxf(mx0, __shfl_xor_sync(0xffffffffu, mx0, 2));
        mx1 = fmaxf(mx1, __shfl_xor_sync(0xffffffffu, mx1, 1));
        mx1 = fmaxf(mx1, __shfl_xor_sync(0xffffffffu, mx1, 2));

        float mn0 = fmaxf(m_[0], mx0), mn1 = fmaxf(m_[1], mx1);
        float al0 = __expf(m_[0] - mn0), al1 = __expf(m_[1] - mn1);
        m_[0] = mn0; m_[1] = mn1;

        float rs0 = 0.0f, rs1 = 0.0f;
#pragma unroll
        for (int nt = 0; nt < 8; nt++) {
            acc[nt][0] = __expf(acc[nt][0] - mn0); rs0 += acc[nt][0];
            acc[nt][1] = __expf(acc[nt][1] - mn0); rs0 += acc[nt][1];
            acc[nt][2] = __expf(acc[nt][2] - mn1); rs1 += acc[nt][2];
            acc[nt][3] = __expf(acc[nt][3] - mn1); rs1 += acc[nt][3];
        }
        rs0 += __shfl_xor_sync(0xffffffffu, rs0, 1);
        rs0 += __shfl_xor_sync(0xffffffffu, rs0, 2);
        rs1 += __shfl_xor_sync(0xffffffffu, rs1, 1);
        rs1 += __shfl_xor_sync(0xffffffffu, rs1, 2);

        l_[0] = l_[0] * al0 + rs0;
        l_[1] = l_[1] * al1 + rs1;
#pragma unroll
        for (int n = 0; n < 16; n++) {
            o_[n][0] *= al0; o_[n][1] *= al0;
            o_[n][2] *= al1; o_[n][3] *= al1;
        }

        {
            int pbase = w * 1024;
            int lane0 = r * 4 + (c2 & 3);
            int reg0  = 2 * (c2 >> 2);
#pragma unroll
            for (int nt = 0; nt < 8; nt++) {
                int a0 = pbase + nt * 128 + lane0 * 4 + reg0;
                Ps[a0]     = f2tf32(acc[nt][0]);
                Ps[a0 + 4] = f2tf32(acc[nt][1]);
                Ps[a0 + 1] = f2tf32(acc[nt][2]);
                Ps[a0 + 5] = f2tf32(acc[nt][3]);
            }
        }
        __syncwarp();

        {
            int pbase = w * 1024;
#pragma unroll
            for (int ks = 0; ks < 8; ks++) {
                uint4 a = *(const uint4*)&Ps[pbase + ks * 128 + lane * 4];
#pragma unroll
                for (int nt = 0; nt < 16; nt++) {
                    uint2 b = *(const uint2*)&Vs[((ks * 16 + nt) * 32 + lane) * 2];
                    mma_tf32(o_[nt][0], o_[nt][1], o_[nt][2], o_[nt][3],
                             a.x, a.y, a.z, a.w, b.x, b.y);
                }
            }
        }
        __syncthreads();
    }

    float inv0 = 1.0f / l_[0], inv1 = 1.0f / l_[1];
#pragma unroll
    for (int nt = 0; nt < 16; nt++) {
        int col = h * D_HEAD + nt * 8 + c2;
        *(float2*)&O[(size_t)rg0 * QCOLS + col] =
            make_float2(o_[nt][0] * inv0, o_[nt][1] * inv0);
        *(float2*)&O[(size_t)rg1 * QCOLS + col] =
            make_float2(o_[nt][2] * inv1, o_[nt][3] * inv1);
    }
}

// ============================================================================
// kernel_launch
// ============================================================================
extern "C" void kernel_launch(void* const* d_in, const int* in_sizes, int n_in,
                              void* d_out, int out_size) {
    (void)in_sizes; (void)n_in; (void)out_size;
    const float* hidden = (const float*)d_in[0];
    const int*   pos    = (const int*)d_in[2];
    const float* Wq     = (const float*)d_in[3];
    const float* Wk     = (const float*)d_in[4];
    const float* Wv     = (const float*)d_in[5];
    const float* Wo     = (const float*)d_in[6];
    float* out = (float*)d_out;

    float *Qp, *Kp, *Vp, *Ap;
    cudaGetSymbolAddress((void**)&Qp, g_Q);
    cudaGetSymbolAddress((void**)&Kp, g_K);
    cudaGetSymbolAddress((void**)&Vp, g_V);
    cudaGetSymbolAddress((void**)&Ap, g_A);

    cudaFuncSetAttribute(tf32_gemm_nt,
                         cudaFuncAttributeMaxDynamicSharedMemorySize, SMEM_GEMM);
    cudaFuncSetAttribute(flash_tf32,
                         cudaFuncAttributeMaxDynamicSharedMemorySize, SMEM_FA);

    dim3 blk(256);
    tf32_gemm_nt<<<dim3(QCOLS / 128, S_LEN / 128), blk, SMEM_GEMM>>>(hidden, Wq, Qp, S_LEN, QCOLS, HIDDEN);
    tf32_gemm_nt<<<dim3(KCOLS / 128, S_LEN / 128), blk, SMEM_GEMM>>>(hidden, Wk, Kp, S_LEN, KCOLS, HIDDEN);
    tf32_gemm_nt<<<dim3(KCOLS / 128, S_LEN / 128), blk, SMEM_GEMM>>>(hidden, Wv, Vp, S_LEN, KCOLS, HIDDEN);
    rope_kernel<<<(S_LEN * HQ * 64 + 255) / 256, 256>>>(Qp, pos, HQ, S_LEN * HQ * 64);
    rope_kernel<<<(S_LEN * HK * 64 + 255) / 256, 256>>>(Kp, pos, HK, S_LEN * HK * 64);
    flash_tf32<<<dim3(S_LEN / 128, HQ), blk, SMEM_FA>>>(Qp, Kp, Vp, Ap);
    tf32_gemm_nt<<<dim3(QCOLS / 128, S_LEN / 128), blk, SMEM_GEMM>>>(Ap, Wo, out, S_LEN, QCOLS, HIDDEN);
}

// round 11
// speedup vs baseline: 1.9941x; 1.9941x over previous
#include <cuda_runtime.h>
#include <cuda_fp16.h>
#include <math.h>
#include <stdint.h>

#define S_LEN   3072
#define HIDDEN  2048
#define HQ      16
#define HK      2
#define D_HEAD  128
#define QCOLS   (HQ * D_HEAD)   // 2048
#define KCOLS   (HK * D_HEAD)   // 256

// ---------------- scratch (device globals, fp16) ----------------------------
__device__ __half g_Q[S_LEN * QCOLS];   // 12 MB (pre-scaled by 1/sqrt(D) in rope)
__device__ __half g_K[S_LEN * KCOLS];
__device__ __half g_V[S_LEN * KCOLS];
__device__ __half g_A[S_LEN * QCOLS];

// ============================================================================
// Helpers
// ============================================================================
__device__ __forceinline__ uint32_t f22h2(float a, float b) {
    __half2 h = __floats2half2_rn(a, b);   // low = a, high = b
    return *(uint32_t*)&h;
}

// m16n8k16 f16 mma, fp32 accumulate.
// A frag (lane g=l>>2, c=l&3): a0=(g,2c..2c+1) a1=(g+8,2c..) a2=(g,2c+8..) a3=(g+8,2c+8..)
// B frag: b0=(k=2c..2c+1, n=g) b1=(k=2c+8.., n=g)
// D frag: d0=(g,2c) d1=(g,2c+1) d2=(g+8,2c) d3=(g+8,2c+1)
__device__ __forceinline__ void mma_f16(float& d0, float& d1, float& d2, float& d3,
                                        uint32_t a0, uint32_t a1, uint32_t a2, uint32_t a3,
                                        uint32_t b0, uint32_t b1) {
    asm volatile(
        "mma.sync.aligned.m16n8k16.row.col.f32.f16.f16.f32 "
        "{%0,%1,%2,%3}, {%4,%5,%6,%7}, {%8,%9}, {%0,%1,%2,%3};\n"
        : "+f"(d0), "+f"(d1), "+f"(d2), "+f"(d3)
        : "r"(a0), "r"(a1), "r"(a2), "r"(a3), "r"(b0), "r"(b1));
}

// ============================================================================
// FP16 tensor-core GEMM: C[M,N] = A[M,K] * B[N,K]^T
// BM=BN=128, BK=32 (2 k16-steps), 256 threads (8 warps 2x4), warp tile 64x32.
// A_HALF: A is __half (row stride K); else fp32. C_HALF: C is __half; else f32.
// B always fp32. Fragment-permuted smem; register-prefetch pipeline (R6-style).
// Requires M%128==0, N%128==0, K%32==0.
// ============================================================================
template<int A_HALF, int C_HALF>
__global__ __launch_bounds__(256, 1)
void hgemm_nt(const void* __restrict__ Av, const float* __restrict__ Bv,
              void* __restrict__ Cv, int M, int N, int K) {
    __shared__ uint32_t As[2048];   // [ks2][msub8][lane32][reg4]
    __shared__ uint32_t Bs[2048];   // [ks2][nsub16][lane32][reg2]

    const int t    = threadIdx.x;
    const int warp = t >> 5;
    const int lane = t & 31;
    const int bm   = blockIdx.y * 128;
    const int bn   = blockIdx.x * 128;
    const int wm4  = (warp >> 2) * 4;
    const int wn8  = (warp & 3) * 4;

    // ---- B loader geometry (fp32, 4 float4 tasks) ----
    int bIdx[4]; const float* bP[4];
#pragma unroll
    for (int i = 0; i < 4; i++) {
        int id = t + i * 256, row = id >> 3, ch = id & 7;
        int nsub = row >> 3, g = row & 7, kk = (ch & 3) * 4, ks = ch >> 2;
        bIdx[i] = ((ks * 16 + nsub) * 32 + g * 4 + ((kk & 7) >> 1)) * 2 + (kk >> 3);
        bP[i]   = Bv + (size_t)(bn + row) * K + ch * 4;
    }
    // ---- A loader geometry ----
    int aIdx[4];
    const float*  aPf[4];
    const __half* aPh[2];
    if (A_HALF) {
#pragma unroll
        for (int i = 0; i < 2; i++) {
            int id = t + i * 256, row = id >> 2, ch = id & 3;
            int msub = row >> 4, r8 = (row >> 3) & 1, g = row & 7;
            aIdx[i] = (((ch >> 1) * 8 + msub) * 32 + g * 4) * 4 + r8 + 2 * (ch & 1);
            aPh[i]  = (const __half*)Av + (size_t)(bm + row) * K + ch * 8;
        }
    } else {
#pragma unroll
        for (int i = 0; i < 4; i++) {
            int id = t + i * 256, row = id >> 3, ch = id & 7;
            int msub = row >> 4, r8 = (row >> 3) & 1, g = row & 7;
            int kk = (ch & 3) * 4, ks = ch >> 2;
            aIdx[i] = ((ks * 8 + msub) * 32 + g * 4 + ((kk & 7) >> 1)) * 4 + r8 + 2 * (kk >> 3);
            aPf[i]  = (const float*)Av + (size_t)(bm + row) * K + ch * 4;
        }
    }

    float acc[4][4][4];
#pragma unroll
    for (int m = 0; m < 4; m++)
#pragma unroll
        for (int n = 0; n < 4; n++)
#pragma unroll
            for (int r = 0; r < 4; r++) acc[m][n][r] = 0.0f;

    // ---- prefetch first tile ----
    float4 pb[4], paf[4];
    uint4  pah[2];
#pragma unroll
    for (int i = 0; i < 4; i++) pb[i] = *(const float4*)bP[i];
    if (A_HALF) {
#pragma unroll
        for (int i = 0; i < 2; i++) pah[i] = *(const uint4*)aPh[i];
    } else {
#pragma unroll
        for (int i = 0; i < 4; i++) paf[i] = *(const float4*)aPf[i];
    }

    for (int k0 = 0; k0 < K; k0 += 32) {
        // ---- store tile (convert to fp16 on the way in) ----
#pragma unroll
        for (int i = 0; i < 4; i++) {
            Bs[bIdx[i]]     = f22h2(pb[i].x, pb[i].y);
            Bs[bIdx[i] + 2] = f22h2(pb[i].z, pb[i].w);
        }
        if (A_HALF) {
#pragma unroll
            for (int i = 0; i < 2; i++) {
                As[aIdx[i] + 0]  = pah[i].x;
                As[aIdx[i] + 4]  = pah[i].y;
                As[aIdx[i] + 8]  = pah[i].z;
                As[aIdx[i] + 12] = pah[i].w;
            }
        } else {
#pragma unroll
            for (int i = 0; i < 4; i++) {
                As[aIdx[i]]     = f22h2(paf[i].x, paf[i].y);
                As[aIdx[i] + 4] = f22h2(paf[i].z, paf[i].w);
            }
        }
        __syncthreads();

        // ---- prefetch next ----
        if (k0 + 32 < K) {
#pragma unroll
            for (int i = 0; i < 4; i++) { bP[i] += 32; pb[i] = *(const float4*)bP[i]; }
            if (A_HALF) {
#pragma unroll
                for (int i = 0; i < 2; i++) { aPh[i] += 32; pah[i] = *(const uint4*)aPh[i]; }
            } else {
#pragma unroll
                for (int i = 0; i < 4; i++) { aPf[i] += 32; paf[i] = *(const float4*)aPf[i]; }
            }
        }

        // ---- compute: 2 k16-steps x (4 msub x 4 nsub) ----
#pragma unroll
        for (int ks = 0; ks < 2; ks++) {
            uint4 af[4];
            uint2 bf[4];
#pragma unroll
            for (int m = 0; m < 4; m++)
                af[m] = *(const uint4*)&As[((ks * 8 + wm4 + m) * 32 + lane) * 4];
#pragma unroll
            for (int n = 0; n < 4; n++)
                bf[n] = *(const uint2*)&Bs[((ks * 16 + wn8 + n) * 32 + lane) * 2];
#pragma unroll
            for (int m = 0; m < 4; m++)
#pragma unroll
                for (int n = 0; n < 4; n++)
                    mma_f16(acc[m][n][0], acc[m][n][1], acc[m][n][2], acc[m][n][3],
                            af[m].x, af[m].y, af[m].z, af[m].w,
                            bf[n].x, bf[n].y);
        }
        __syncthreads();
    }

    // ---- epilogue ----
    const int wm = (warp >> 2) * 64;
    const int wn = (warp & 3) * 32;
    const int lr = lane >> 2;
    const int lc = (lane & 3) * 2;
#pragma unroll
    for (int m = 0; m < 4; m++) {
#pragma unroll
        for (int n = 0; n < 4; n++) {
            int r0 = bm + wm + m * 16 + lr;
            int c0 = bn + wn + n * 8 + lc;
            if (C_HALF) {
                __half* C = (__half*)Cv;
                *(uint32_t*)&C[(size_t)r0 * N + c0] =
                    f22h2(acc[m][n][0], acc[m][n][1]);
                *(uint32_t*)&C[(size_t)(r0 + 8) * N + c0] =
                    f22h2(acc[m][n][2], acc[m][n][3]);
            } else {
                float* C = (float*)Cv;
                *(float2*)&C[(size_t)r0 * N + c0] =
                    make_float2(acc[m][n][0], acc[m][n][1]);
                *(float2*)&C[(size_t)(r0 + 8) * N + c0] =
                    make_float2(acc[m][n][2], acc[m][n][3]);
            }
        }
    }
}

// ============================================================================
// RoPE in-place on fp16, with optional output scaling (softmax scale for Q).
// ============================================================================
__global__ void rope_half(__half* __restrict__ x, const int* __restrict__ pos,
                          int nheads, int total, float oscale) {
    int idx = blockIdx.x * blockDim.x + threadIdx.x;
    if (idx >= total) return;
    int fi = idx & 63;
    int h  = (idx >> 6) % nheads;
    int s  = idx / (nheads * 64);

    float p    = (float)pos[s];
    float invf = powf(10000.0f, -((float)fi) / 64.0f);
    float sn, cs;
    sincosf(p * invf, &sn, &cs);

    size_t base = (size_t)s * (nheads * D_HEAD) + h * D_HEAD + fi;
    float x1 = __half2float(x[base]);
    float x2 = __half2float(x[base + 64]);
    x[base]      = __float2half((x1 * cs - x2 * sn) * oscale);
    x[base + 64] = __float2half((x2 * cs + x1 * sn) * oscale);
}

// ============================================================================
// FP16 tensor-core causal flash attention.
// Block = 256 threads (8 warps) x (q-tile 128, head). Warp w owns q-rows
// [w*16,w*16+16). K/V tiles of 64 keys. GQA: q-head h -> kv-head (h & 1).
// Q pre-scaled by 1/sqrt(D) in rope.
// Smem (u32): Qs[8ks][8msub][32][4]=8192 | Ks[8ks][8nsub][32][2]=4096 |
//             Vs[4ks][16nsub][32][2]=4096 | Ps[8w][4ks][32][4]=4096  -> 80 KB
// ============================================================================
#define SMEM_FAH (20480 * 4)

__global__ __launch_bounds__(256, 1)
void flash_f16(const __half* __restrict__ Q, const __half* __restrict__ Kb,
               const __half* __restrict__ Vb, __half* __restrict__ O) {
    extern __shared__ uint32_t sm[];
    uint32_t* Qs = sm;            // 8192
    uint32_t* Ks = sm + 8192;     // 4096
    uint32_t* Vs = sm + 12288;    // 4096
    uint32_t* Ps = sm + 16384;    // 4096

    const int t    = threadIdx.x;
    const int w    = t >> 5;
    const int lane = t & 31;
    const int qt   = gridDim.x - 1 - blockIdx.x;   // longest blocks first
    const int h    = blockIdx.y;
    const int q0   = qt * 128;
    const int kvoff = (h & 1) * D_HEAD;

    // ---- load Q tile (128x128 halves) into A-fragment smem ----
#pragma unroll
    for (int i = 0; i < 8; i++) {
        int id  = t + i * 256;
        int row = id >> 4;
        int ch  = id & 15;          // chunk of 8 d
        uint4 qv = *(const uint4*)&Q[(size_t)(q0 + row) * QCOLS + h * D_HEAD + ch * 8];
        int msub = row >> 4, r8 = (row >> 3) & 1, g = row & 7;
        int base = (((ch >> 1) * 8 + msub) * 32 + g * 4) * 4 + r8 + 2 * (ch & 1);
        Qs[base + 0]  = qv.x;
        Qs[base + 4]  = qv.y;
        Qs[base + 8]  = qv.z;
        Qs[base + 12] = qv.w;
    }

    float m_[2] = {-INFINITY, -INFINITY};
    float l_[2] = {0.0f, 0.0f};
    float o_[16][4];
#pragma unroll
    for (int n = 0; n < 16; n++)
#pragma unroll
        for (int r = 0; r < 4; r++) o_[n][r] = 0.0f;

    const int nkt = qt * 2 + 2;
    const int r   = lane >> 2;
    const int c2  = (lane & 3) * 2;
    const int rg0 = q0 + w * 16 + r;
    const int rg1 = rg0 + 8;

    // ---- prefetch tile 0 (K: 4 uint4; V: 4 pairs of uint2) ----
    uint4 kf[4];
    uint2 vfa[4], vfb[4];
#pragma unroll
    for (int i = 0; i < 4; i++) {
        int id = t + i * 256;
        {
            int row = id >> 4, ch = id & 15;
            kf[i] = *(const uint4*)&Kb[(size_t)row * KCOLS + kvoff + ch * 8];
        }
        {
            int kp = id >> 5, dc = id & 31;
            vfa[i] = *(const uint2*)&Vb[(size_t)(kp * 2)     * KCOLS + kvoff + dc * 4];
            vfb[i] = *(const uint2*)&Vb[(size_t)(kp * 2 + 1) * KCOLS + kvoff + dc * 4];
        }
    }

    for (int kt = 0; kt < nkt; kt++) {
        const int k0 = kt * 64;

        // ---- scatter K, V into fragment smem ----
#pragma unroll
        for (int i = 0; i < 4; i++) {
            int id = t + i * 256;
            {   // K: B-op (n=key, k=d)
                int row = id >> 4, ch = id & 15;
                int nsub = row >> 3, g = row & 7;
                int base = (((ch >> 1) * 8 + nsub) * 32 + g * 4) * 2 + (ch & 1);
                Ks[base + 0] = kf[i].x;
                Ks[base + 2] = kf[i].y;
                Ks[base + 4] = kf[i].z;
                Ks[base + 6] = kf[i].w;
            }
            {   // V: B-op (n=d, k=key); key-pair transpose
                int kp = id >> 5, dc = id & 31;
                int ks = kp >> 3, lpair = kp & 3, reg = (kp >> 2) & 1;
                int base = ((ks * 16 + (dc >> 1)) * 32 + (dc & 1) * 16 + lpair) * 2 + reg;
                __half2 a0 = *(__half2*)&vfa[i].x;
                __half2 b0 = *(__half2*)&vfb[i].x;
                __half2 a1 = *(__half2*)&vfa[i].y;
                __half2 b1 = *(__half2*)&vfb[i].y;
                __half2 j0 = __lows2half2(a0, b0);
                __half2 j1 = __highs2half2(a0, b0);
                __half2 j2 = __lows2half2(a1, b1);
                __half2 j3 = __highs2half2(a1, b1);
                Vs[base + 0]  = *(uint32_t*)&j0;
                Vs[base + 8]  = *(uint32_t*)&j1;
                Vs[base + 16] = *(uint32_t*)&j2;
                Vs[base + 24] = *(uint32_t*)&j3;
            }
        }
        __syncthreads();

        // ---- prefetch next tile ----
        if (kt + 1 < nkt) {
            int k0n = (kt + 1) * 64;
#pragma unroll
            for (int i = 0; i < 4; i++) {
                int id = t + i * 256;
                {
                    int row = id >> 4, ch = id & 15;
                    kf[i] = *(const uint4*)&Kb[(size_t)(k0n + row) * KCOLS + kvoff + ch * 8];
                }
                {
                    int kp = id >> 5, dc = id & 31;
                    vfa[i] = *(const uint2*)&Vb[(size_t)(k0n + kp * 2)     * KCOLS + kvoff + dc * 4];
                    vfb[i] = *(const uint2*)&Vb[(size_t)(k0n + kp * 2 + 1) * KCOLS + kvoff + dc * 4];
                }
            }
        }

        // ---- scores: S[16x64] per warp (8 k16-steps) ----
        float acc[8][4];
#pragma unroll
        for (int n = 0; n < 8; n++)
#pragma unroll
            for (int x = 0; x < 4; x++) acc[n][x] = 0.0f;

#pragma unroll
        for (int ks = 0; ks < 8; ks++) {
            uint4 a = *(const uint4*)&Qs[((ks * 8 + w) * 32 + lane) * 4];
#pragma unroll
            for (int nt = 0; nt < 8; nt++) {
                uint2 b = *(const uint2*)&Ks[((ks * 8 + nt) * 32 + lane) * 2];
                mma_f16(acc[nt][0], acc[nt][1], acc[nt][2], acc[nt][3],
                        a.x, a.y, a.z, a.w, b.x, b.y);
            }
        }

        // ---- causal mask ----
        if (kt >= nkt - 2) {
#pragma unroll
            for (int nt = 0; nt < 8; nt++) {
                int cg = k0 + nt * 8 + c2;
                if (cg > rg0)     acc[nt][0] = -1e30f;
                if (cg + 1 > rg0) acc[nt][1] = -1e30f;
                if (cg > rg1)     acc[nt][2] = -1e30f;
                if (cg + 1 > rg1) acc[nt][3] = -1e30f;
            }
        }

        // ---- online softmax ----
        float mx0 = -INFINITY, mx1 = -INFINITY;
#pragma unroll
        for (int nt = 0; nt < 8; nt++) {
            mx0 = fmaxf(mx0, fmaxf(acc[nt][0], acc[nt][1]));
            mx1 = fmaxf(mx1, fmaxf(acc[nt][2], acc[nt][3]));
        }
        mx0 = fmaxf(mx0, __shfl_xor_sync(0xffffffffu, mx0, 1));
        mx0 = fmaxf(mx0, __shfl_xor_sync(0xffffffffu, mx0, 2));
        mx1 = fmaxf(mx1, __shfl_xor_sync(0xffffffffu, mx1, 1));
        mx1 = fmaxf(mx1, __shfl_xor_sync(0xffffffffu, mx1, 2));

        float mn0 = fmaxf(m_[0], mx0), mn1 = fmaxf(m_[1], mx1);
        float al0 = __expf(m_[0] - mn0), al1 = __expf(m_[1] - mn1);
        m_[0] = mn0; m_[1] = mn1;

        float rs0 = 0.0f, rs1 = 0.0f;
#pragma unroll
        for (int nt = 0; nt < 8; nt++) {
            acc[nt][0] = __expf(acc[nt][0] - mn0); rs0 += acc[nt][0];
            acc[nt][1] = __expf(acc[nt][1] - mn0); rs0 += acc[nt][1];
            acc[nt][2] = __expf(acc[nt][2] - mn1); rs1 += acc[nt][2];
            acc[nt][3] = __expf(acc[nt][3] - mn1); rs1 += acc[nt][3];
        }
        rs0 += __shfl_xor_sync(0xffffffffu, rs0, 1);
        rs0 += __shfl_xor_sync(0xffffffffu, rs0, 2);
        rs1 += __shfl_xor_sync(0xffffffffu, rs1, 1);
        rs1 += __shfl_xor_sync(0xffffffffu, rs1, 2);

        l_[0] = l_[0] * al0 + rs0;
        l_[1] = l_[1] * al1 + rs1;
#pragma unroll
        for (int n = 0; n < 16; n++) {
            o_[n][0] *= al0; o_[n][1] *= al0;
            o_[n][2] *= al1; o_[n][3] *= al1;
        }

        // ---- P -> warp-private A-fragment smem (each thread hits own lane) ----
        {
            int pb = w * 512;
#pragma unroll
            for (int nt = 0; nt < 8; nt++) {
                int a0 = pb + ((nt >> 1) * 32 + lane) * 4 + 2 * (nt & 1);
                Ps[a0]     = f22h2(acc[nt][0], acc[nt][1]);   // rows r   (reg r8=0)
                Ps[a0 + 1] = f22h2(acc[nt][2], acc[nt][3]);   // rows r+8 (reg r8=1)
            }
        }
        __syncwarp();

        // ---- O += P . V  (4 k16-steps x 16 d-subtiles) ----
        {
            int pb = w * 512;
#pragma unroll
            for (int ks = 0; ks < 4; ks++) {
                uint4 a = *(const uint4*)&Ps[pb + (ks * 32 + lane) * 4];
#pragma unroll
                for (int nt = 0; nt < 16; nt++) {
                    uint2 b = *(const uint2*)&Vs[((ks * 16 + nt) * 32 + lane) * 2];
                    mma_f16(o_[nt][0], o_[nt][1], o_[nt][2], o_[nt][3],
                            a.x, a.y, a.z, a.w, b.x, b.y);
                }
            }
        }
        __syncthreads();
    }

    // ---- epilogue: normalize, write fp16 [S, HQ*D] ----
    float inv0 = 1.0f / l_[0], inv1 = 1.0f / l_[1];
#pragma unroll
    for (int nt = 0; nt < 16; nt++) {
        int col = h * D_HEAD + nt * 8 + c2;
        *(uint32_t*)&O[(size_t)rg0 * QCOLS + col] =
            f22h2(o_[nt][0] * inv0, o_[nt][1] * inv0);
        *(uint32_t*)&O[(size_t)rg1 * QCOLS + col] =
            f22h2(o_[nt][2] * inv1, o_[nt][3] * inv1);
    }
}

// ============================================================================
// kernel_launch
// inputs: 0 hidden f32, 1 mask (unused), 2 pos i32, 3 Wq, 4 Wk, 5 Wv, 6 Wo
// ============================================================================
extern "C" void kernel_launch(void* const* d_in, const int* in_sizes, int n_in,
                              void* d_out, int out_size) {
    (void)in_sizes; (void)n_in; (void)out_size;
    const float* hidden = (const float*)d_in[0];
    const int*   pos    = (const int*)d_in[2];
    const float* Wq     = (const float*)d_in[3];
    const float* Wk     = (const float*)d_in[4];
    const float* Wv     = (const float*)d_in[5];
    const float* Wo     = (const float*)d_in[6];
    float* out = (float*)d_out;

    __half *Qp, *Kp, *Vp, *Ap;
    cudaGetSymbolAddress((void**)&Qp, g_Q);
    cudaGetSymbolAddress((void**)&Kp, g_K);
    cudaGetSymbolAddress((void**)&Vp, g_V);
    cudaGetSymbolAddress((void**)&Ap, g_A);

    cudaFuncSetAttribute(flash_f16,
                         cudaFuncAttributeMaxDynamicSharedMemorySize, SMEM_FAH);

    const float SCALE = 0.08838834764831845f;   // 1/sqrt(128)
    dim3 blk(256);
    // projections (fp16 m16n8k16 tensor cores), fp16 outputs
    hgemm_nt<0, 1><<<dim3(QCOLS / 128, S_LEN / 128), blk>>>(hidden, Wq, Qp, S_LEN, QCOLS, HIDDEN);
    hgemm_nt<0, 1><<<dim3(KCOLS / 128, S_LEN / 128), blk>>>(hidden, Wk, Kp, S_LEN, KCOLS, HIDDEN);
    hgemm_nt<0, 1><<<dim3(KCOLS / 128, S_LEN / 128), blk>>>(hidden, Wv, Vp, S_LEN, KCOLS, HIDDEN);
    // RoPE (Q also gets the softmax scale folded in)
    rope_half<<<(S_LEN * HQ * 64 + 255) / 256, 256>>>(Qp, pos, HQ, S_LEN * HQ * 64, SCALE);
    rope_half<<<(S_LEN * HK * 64 + 255) / 256, 256>>>(Kp, pos, HK, S_LEN * HK * 64, 1.0f);
    // fp16 causal flash attention: 24 q-tiles x 16 heads
    flash_f16<<<dim3(S_LEN / 128, HQ), blk, SMEM_FAH>>>(Qp, Kp, Vp, Ap);
    // output projection: fp16 A, fp32 out
    hgemm_nt<1, 0><<<dim3(QCOLS / 128, S_LEN / 128), blk>>>(Ap, Wo, out, S_LEN, QCOLS, HIDDEN);
}

// round 13
// speedup vs baseline: 2.4399x; 1.2236x over previous
#include <cuda_runtime.h>
#include <cuda_fp16.h>
#include <math.h>
#include <stdint.h>

#define S_LEN   3072
#define HIDDEN  2048
#define HQ      16
#define HK      2
#define D_HEAD  128
#define QCOLS   (HQ * D_HEAD)   // 2048
#define KCOLS   (HK * D_HEAD)   // 256

// ---------------- scratch (device globals, fp16) ----------------------------
__device__ __half g_Q[S_LEN * QCOLS];   // pre-scaled by 1/sqrt(D) in rope
__device__ __half g_K[S_LEN * KCOLS];
__device__ __half g_V[S_LEN * KCOLS];
__device__ __half g_A[S_LEN * QCOLS];

// ============================================================================
// Helpers
// ============================================================================
__device__ __forceinline__ uint32_t f22h2(float a, float b) {
    __half2 h = __floats2half2_rn(a, b);
    return *(uint32_t*)&h;
}

__device__ __forceinline__ void mma_f16(float& d0, float& d1, float& d2, float& d3,
                                        uint32_t a0, uint32_t a1, uint32_t a2, uint32_t a3,
                                        uint32_t b0, uint32_t b1) {
    asm volatile(
        "mma.sync.aligned.m16n8k16.row.col.f32.f16.f16.f32 "
        "{%0,%1,%2,%3}, {%4,%5,%6,%7}, {%8,%9}, {%0,%1,%2,%3};\n"
        : "+f"(d0), "+f"(d1), "+f"(d2), "+f"(d3)
        : "r"(a0), "r"(a1), "r"(a2), "r"(a3), "r"(b0), "r"(b1));
}

// ============================================================================
// Fused QKV projection: [hidden][Wq|Wk|Wv] -> g_Q | g_K | g_V  (fp16 out)
// Grid: x = 20 n-tiles (16 Q, 2 K, 2 V), y = 24 m-tiles.
// BM=BN=128, BK=32 (2 k16-steps), 256 threads, warp tile 64x32.
// Double-buffered smem, ONE sync per k-iter, 2 CTAs/SM.
// ============================================================================
__global__ __launch_bounds__(256, 2)
void qkv_gemm(const float* __restrict__ hidden, const float* __restrict__ Wq,
              const float* __restrict__ Wk, const float* __restrict__ Wv) {
    __shared__ uint32_t As[2][2048];
    __shared__ uint32_t Bs[2][2048];

    const int t    = threadIdx.x;
    const int warp = t >> 5;
    const int lane = t & 31;
    const int bm   = blockIdx.y * 128;
    const int bn   = blockIdx.x * 128;
    const int wm4  = (warp >> 2) * 4;
    const int wn8  = (warp & 3) * 4;
    const int K    = HIDDEN;

    // ---- per-block output / weight selection ----
    const float* Bv;
    __half* Cv;
    int Ncols, cb;
    if (bn < QCOLS)               { Bv = Wq + (size_t)bn * K;                 Cv = g_Q; Ncols = QCOLS; cb = bn; }
    else if (bn < QCOLS + KCOLS)  { Bv = Wk + (size_t)(bn - QCOLS) * K;       Cv = g_K; Ncols = KCOLS; cb = bn - QCOLS; }
    else                          { Bv = Wv + (size_t)(bn - QCOLS - KCOLS) * K; Cv = g_V; Ncols = KCOLS; cb = bn - QCOLS - KCOLS; }

    // ---- loader geometry (4 float4 tasks each for A and B) ----
    int aIdx[4], bIdx[4];
    const float* aP[4];
    const float* bP[4];
#pragma unroll
    for (int i = 0; i < 4; i++) {
        int id = t + i * 256, row = id >> 3, ch = id & 7;
        int kk = (ch & 3) * 4, ks = ch >> 2;
        {
            int msub = row >> 4, r8 = (row >> 3) & 1, g = row & 7;
            aIdx[i] = ((ks * 8 + msub) * 32 + g * 4 + ((kk & 7) >> 1)) * 4 + r8 + 2 * (kk >> 3);
            aP[i]   = hidden + (size_t)(bm + row) * K + ch * 4;
        }
        {
            int nsub = row >> 3, g = row & 7;
            bIdx[i] = ((ks * 16 + nsub) * 32 + g * 4 + ((kk & 7) >> 1)) * 2 + (kk >> 3);
            bP[i]   = Bv + (size_t)row * K + ch * 4;
        }
    }

    float acc[4][4][4];
#pragma unroll
    for (int m = 0; m < 4; m++)
#pragma unroll
        for (int n = 0; n < 4; n++)
#pragma unroll
            for (int r = 0; r < 4; r++) acc[m][n][r] = 0.0f;

    // ---- preload tile 0 into buffer 0 ----
    {
        float4 pa[4], pb[4];
#pragma unroll
        for (int i = 0; i < 4; i++) { pa[i] = *(const float4*)aP[i]; pb[i] = *(const float4*)bP[i]; }
#pragma unroll
        for (int i = 0; i < 4; i++) {
            As[0][aIdx[i]]     = f22h2(pa[i].x, pa[i].y);
            As[0][aIdx[i] + 4] = f22h2(pa[i].z, pa[i].w);
            Bs[0][bIdx[i]]     = f22h2(pb[i].x, pb[i].y);
            Bs[0][bIdx[i] + 2] = f22h2(pb[i].z, pb[i].w);
        }
    }
    __syncthreads();

    const int NS = K >> 5;
    for (int s = 0; s < NS; s++) {
        const int buf = s & 1;
        float4 pa[4], pb[4];
        const bool more = (s + 1 < NS);
        if (more) {
#pragma unroll
            for (int i = 0; i < 4; i++) {
                aP[i] += 32; bP[i] += 32;
                pa[i] = *(const float4*)aP[i];
                pb[i] = *(const float4*)bP[i];
            }
        }

#pragma unroll
        for (int ks = 0; ks < 2; ks++) {
            uint4 af[4];
            uint2 bf[4];
#pragma unroll
            for (int m = 0; m < 4; m++)
                af[m] = *(const uint4*)&As[buf][((ks * 8 + wm4 + m) * 32 + lane) * 4];
#pragma unroll
            for (int n = 0; n < 4; n++)
                bf[n] = *(const uint2*)&Bs[buf][((ks * 16 + wn8 + n) * 32 + lane) * 2];
#pragma unroll
            for (int m = 0; m < 4; m++)
#pragma unroll
                for (int n = 0; n < 4; n++)
                    mma_f16(acc[m][n][0], acc[m][n][1], acc[m][n][2], acc[m][n][3],
                            af[m].x, af[m].y, af[m].z, af[m].w,
                            bf[n].x, bf[n].y);
        }

        if (more) {
#pragma unroll
            for (int i = 0; i < 4; i++) {
                As[1 - buf][aIdx[i]]     = f22h2(pa[i].x, pa[i].y);
                As[1 - buf][aIdx[i] + 4] = f22h2(pa[i].z, pa[i].w);
                Bs[1 - buf][bIdx[i]]     = f22h2(pb[i].x, pb[i].y);
                Bs[1 - buf][bIdx[i] + 2] = f22h2(pb[i].z, pb[i].w);
            }
        }
        __syncthreads();
    }

    // ---- epilogue (fp16) ----
    const int wm = (warp >> 2) * 64;
    const int wn = (warp & 3) * 32;
    const int lr = lane >> 2;
    const int lc = (lane & 3) * 2;
#pragma unroll
    for (int m = 0; m < 4; m++) {
#pragma unroll
        for (int n = 0; n < 4; n++) {
            int r0 = bm + wm + m * 16 + lr;
            int c0 = cb + wn + n * 8 + lc;
            *(uint32_t*)&Cv[(size_t)r0 * Ncols + c0] =
                f22h2(acc[m][n][0], acc[m][n][1]);
            *(uint32_t*)&Cv[(size_t)(r0 + 8) * Ncols + c0] =
                f22h2(acc[m][n][2], acc[m][n][3]);
        }
    }
}

// ============================================================================
// Output projection: out[M,N] = g_A[M,K](fp16) * Wo[N,K]^T (fp32 out)
// Same double-buffered structure, 2 CTAs/SM.
// ============================================================================
__global__ __launch_bounds__(256, 2)
void wo_gemm(const __half* __restrict__ Av, const float* __restrict__ Bv,
             float* __restrict__ Cv, int M, int N, int K) {
    __shared__ uint32_t As[2][2048];
    __shared__ uint32_t Bs[2][2048];

    const int t    = threadIdx.x;
    const int warp = t >> 5;
    const int lane = t & 31;
    const int bm   = blockIdx.y * 128;
    const int bn   = blockIdx.x * 128;
    const int wm4  = (warp >> 2) * 4;
    const int wn8  = (warp & 3) * 4;

    // A (fp16): 2 uint4 tasks; B (fp32): 4 float4 tasks
    int aIdx[2], bIdx[4];
    const __half* aP[2];
    const float*  bP[4];
#pragma unroll
    for (int i = 0; i < 2; i++) {
        int id = t + i * 256, row = id >> 2, ch = id & 3;
        int msub = row >> 4, r8 = (row >> 3) & 1, g = row & 7;
        aIdx[i] = (((ch >> 1) * 8 + msub) * 32 + g * 4) * 4 + r8 + 2 * (ch & 1);
        aP[i]   = Av + (size_t)(bm + row) * K + ch * 8;
    }
#pragma unroll
    for (int i = 0; i < 4; i++) {
        int id = t + i * 256, row = id >> 3, ch = id & 7;
        int nsub = row >> 3, g = row & 7, kk = (ch & 3) * 4, ks = ch >> 2;
        bIdx[i] = ((ks * 16 + nsub) * 32 + g * 4 + ((kk & 7) >> 1)) * 2 + (kk >> 3);
        bP[i]   = Bv + (size_t)(bn + row) * K + ch * 4;
    }

    float acc[4][4][4];
#pragma unroll
    for (int m = 0; m < 4; m++)
#pragma unroll
        for (int n = 0; n < 4; n++)
#pragma unroll
            for (int r = 0; r < 4; r++) acc[m][n][r] = 0.0f;

    {
        uint4  pa[2];
        float4 pb[4];
#pragma unroll
        for (int i = 0; i < 2; i++) pa[i] = *(const uint4*)aP[i];
#pragma unroll
        for (int i = 0; i < 4; i++) pb[i] = *(const float4*)bP[i];
#pragma unroll
        for (int i = 0; i < 2; i++) {
            As[0][aIdx[i] + 0]  = pa[i].x;
            As[0][aIdx[i] + 4]  = pa[i].y;
            As[0][aIdx[i] + 8]  = pa[i].z;
            As[0][aIdx[i] + 12] = pa[i].w;
        }
#pragma unroll
        for (int i = 0; i < 4; i++) {
            Bs[0][bIdx[i]]     = f22h2(pb[i].x, pb[i].y);
            Bs[0][bIdx[i] + 2] = f22h2(pb[i].z, pb[i].w);
        }
    }
    __syncthreads();

    const int NS = K >> 5;
    for (int s = 0; s < NS; s++) {
        const int buf = s & 1;
        uint4  pa[2];
        float4 pb[4];
        const bool more = (s + 1 < NS);
        if (more) {
#pragma unroll
            for (int i = 0; i < 2; i++) { aP[i] += 32; pa[i] = *(const uint4*)aP[i]; }
#pragma unroll
            for (int i = 0; i < 4; i++) { bP[i] += 32; pb[i] = *(const float4*)bP[i]; }
        }

#pragma unroll
        for (int ks = 0; ks < 2; ks++) {
            uint4 af[4];
            uint2 bf[4];
#pragma unroll
            for (int m = 0; m < 4; m++)
                af[m] = *(const uint4*)&As[buf][((ks * 8 + wm4 + m) * 32 + lane) * 4];
#pragma unroll
            for (int n = 0; n < 4; n++)
                bf[n] = *(const uint2*)&Bs[buf][((ks * 16 + wn8 + n) * 32 + lane) * 2];
#pragma unroll
            for (int m = 0; m < 4; m++)
#pragma unroll
                for (int n = 0; n < 4; n++)
                    mma_f16(acc[m][n][0], acc[m][n][1], acc[m][n][2], acc[m][n][3],
                            af[m].x, af[m].y, af[m].z, af[m].w,
                            bf[n].x, bf[n].y);
        }

        if (more) {
#pragma unroll
            for (int i = 0; i < 2; i++) {
                As[1 - buf][aIdx[i] + 0]  = pa[i].x;
                As[1 - buf][aIdx[i] + 4]  = pa[i].y;
                As[1 - buf][aIdx[i] + 8]  = pa[i].z;
                As[1 - buf][aIdx[i] + 12] = pa[i].w;
            }
#pragma unroll
            for (int i = 0; i < 4; i++) {
                Bs[1 - buf][bIdx[i]]     = f22h2(pb[i].x, pb[i].y);
                Bs[1 - buf][bIdx[i] + 2] = f22h2(pb[i].z, pb[i].w);
            }
        }
        __syncthreads();
    }

    const int wm = (warp >> 2) * 64;
    const int wn = (warp & 3) * 32;
    const int lr = lane >> 2;
    const int lc = (lane & 3) * 2;
#pragma unroll
    for (int m = 0; m < 4; m++) {
#pragma unroll
        for (int n = 0; n < 4; n++) {
            int r0 = bm + wm + m * 16 + lr;
            int c0 = bn + wn + n * 8 + lc;
            *(float2*)&Cv[(size_t)r0 * N + c0] =
                make_float2(acc[m][n][0], acc[m][n][1]);
            *(float2*)&Cv[(size_t)(r0 + 8) * N + c0] =
                make_float2(acc[m][n][2], acc[m][n][3]);
        }
    }
}

// ============================================================================
// RoPE in-place on fp16, with optional output scaling (softmax scale for Q).
// ============================================================================
__global__ void rope_half(__half* __restrict__ x, const int* __restrict__ pos,
                          int nheads, int total, float oscale) {
    int idx = blockIdx.x * blockDim.x + threadIdx.x;
    if (idx >= total) return;
    int fi = idx & 63;
    int h  = (idx >> 6) % nheads;
    int s  = idx / (nheads * 64);

    float p    = (float)pos[s];
    float invf = powf(10000.0f, -((float)fi) / 64.0f);
    float sn, cs;
    sincosf(p * invf, &sn, &cs);

    size_t base = (size_t)s * (nheads * D_HEAD) + h * D_HEAD + fi;
    float x1 = __half2float(x[base]);
    float x2 = __half2float(x[base + 64]);
    x[base]      = __float2half((x1 * cs - x2 * sn) * oscale);
    x[base + 64] = __float2half((x2 * cs + x1 * sn) * oscale);
}

// ============================================================================
// FP16 tensor-core causal flash attention (validated in R11, unchanged).
// ============================================================================
#define SMEM_FAH (20480 * 4)

__global__ __launch_bounds__(256, 1)
void flash_f16(const __half* __restrict__ Q, const __half* __restrict__ Kb,
               const __half* __restrict__ Vb, __half* __restrict__ O) {
    extern __shared__ uint32_t sm[];
    uint32_t* Qs = sm;            // 8192
    uint32_t* Ks = sm + 8192;     // 4096
    uint32_t* Vs = sm + 12288;    // 4096
    uint32_t* Ps = sm + 16384;    // 4096

    const int t    = threadIdx.x;
    const int w    = t >> 5;
    const int lane = t & 31;
    const int qt   = gridDim.x - 1 - blockIdx.x;
    const int h    = blockIdx.y;
    const int q0   = qt * 128;
    const int kvoff = (h & 1) * D_HEAD;

#pragma unroll
    for (int i = 0; i < 8; i++) {
        int id  = t + i * 256;
        int row = id >> 4;
        int ch  = id & 15;
        uint4 qv = *(const uint4*)&Q[(size_t)(q0 + row) * QCOLS + h * D_HEAD + ch * 8];
        int msub = row >> 4, r8 = (row >> 3) & 1, g = row & 7;
        int base = (((ch >> 1) * 8 + msub) * 32 + g * 4) * 4 + r8 + 2 * (ch & 1);
        Qs[base + 0]  = qv.x;
        Qs[base + 4]  = qv.y;
        Qs[base + 8]  = qv.z;
        Qs[base + 12] = qv.w;
    }

    float m_[2] = {-INFINITY, -INFINITY};
    float l_[2] = {0.0f, 0.0f};
    float o_[16][4];
#pragma unroll
    for (int n = 0; n < 16; n++)
#pragma unroll
        for (int r = 0; r < 4; r++) o_[n][r] = 0.0f;

    const int nkt = qt * 2 + 2;
    const int r   = lane >> 2;
    const int c2  = (lane & 3) * 2;
    const int rg0 = q0 + w * 16 + r;
    const int rg1 = rg0 + 8;

    uint4 kf[4];
    uint2 vfa[4], vfb[4];
#pragma unroll
    for (int i = 0; i < 4; i++) {
        int id = t + i * 256;
        {
            int row = id >> 4, ch = id & 15;
            kf[i] = *(const uint4*)&Kb[(size_t)row * KCOLS + kvoff + ch * 8];
        }
        {
            int kp = id >> 5, dc = id & 31;
            vfa[i] = *(const uint2*)&Vb[(size_t)(kp * 2)     * KCOLS + kvoff + dc * 4];
            vfb[i] = *(const uint2*)&Vb[(size_t)(kp * 2 + 1) * KCOLS + kvoff + dc * 4];
        }
    }

    for (int kt = 0; kt < nkt; kt++) {
        const int k0 = kt * 64;

#pragma unroll
        for (int i = 0; i < 4; i++) {
            int id = t + i * 256;
            {
                int row = id >> 4, ch = id & 15;
                int nsub = row >> 3, g = row & 7;
                int base = (((ch >> 1) * 8 + nsub) * 32 + g * 4) * 2 + (ch & 1);
                Ks[base + 0] = kf[i].x;
                Ks[base + 2] = kf[i].y;
                Ks[base + 4] = kf[i].z;
                Ks[base + 6] = kf[i].w;
            }
            {
                int kp = id >> 5, dc = id & 31;
                int ks = kp >> 3, lpair = kp & 3, reg = (kp >> 2) & 1;
                int base = ((ks * 16 + (dc >> 1)) * 32 + (dc & 1) * 16 + lpair) * 2 + reg;
                __half2 a0 = *(__half2*)&vfa[i].x;
                __half2 b0 = *(__half2*)&vfb[i].x;
                __half2 a1 = *(__half2*)&vfa[i].y;
                __half2 b1 = *(__half2*)&vfb[i].y;
                __half2 j0 = __lows2half2(a0, b0);
                __half2 j1 = __highs2half2(a0, b0);
                __half2 j2 = __lows2half2(a1, b1);
                __half2 j3 = __highs2half2(a1, b1);
                Vs[base + 0]  = *(uint32_t*)&j0;
                Vs[base + 8]  = *(uint32_t*)&j1;
                Vs[base + 16] = *(uint32_t*)&j2;
                Vs[base + 24] = *(uint32_t*)&j3;
            }
        }
        __syncthreads();

        if (kt + 1 < nkt) {
            int k0n = (kt + 1) * 64;
#pragma unroll
            for (int i = 0; i < 4; i++) {
                int id = t + i * 256;
                {
                    int row = id >> 4, ch = id & 15;
                    kf[i] = *(const uint4*)&Kb[(size_t)(k0n + row) * KCOLS + kvoff + ch * 8];
                }
                {
                    int kp = id >> 5, dc = id & 31;
                    vfa[i] = *(const uint2*)&Vb[(size_t)(k0n + kp * 2)     * KCOLS + kvoff + dc * 4];
                    vfb[i] = *(const uint2*)&Vb[(size_t)(k0n + kp * 2 + 1) * KCOLS + kvoff + dc * 4];
                }
            }
        }

        float acc[8][4];
#pragma unroll
        for (int n = 0; n < 8; n++)
#pragma unroll
            for (int x = 0; x < 4; x++) acc[n][x] = 0.0f;

#pragma unroll
        for (int ks = 0; ks < 8; ks++) {
            uint4 a = *(const uint4*)&Qs[((ks * 8 + w) * 32 + lane) * 4];
#pragma unroll
            for (int nt = 0; nt < 8; nt++) {
                uint2 b = *(const uint2*)&Ks[((ks * 8 + nt) * 32 + lane) * 2];
                mma_f16(acc[nt][0], acc[nt][1], acc[nt][2], acc[nt][3],
                        a.x, a.y, a.z, a.w, b.x, b.y);
            }
        }

        if (kt >= nkt - 2) {
#pragma unroll
            for (int nt = 0; nt < 8; nt++) {
                int cg = k0 + nt * 8 + c2;
                if (cg > rg0)     acc[nt][0] = -1e30f;
                if (cg + 1 > rg0) acc[nt][1] = -1e30f;
                if (cg > rg1)     acc[nt][2] = -1e30f;
                if (cg + 1 > rg1) acc[nt][3] = -1e30f;
            }
        }

        float mx0 = -INFINITY, mx1 = -INFINITY;
#pragma unroll
        for (int nt = 0; nt < 8; nt++) {
            mx0 = fmaxf(mx0, fmaxf(acc[nt][0], acc[nt][1]));
            mx1 = fmaxf(mx1, fmaxf(acc[nt][2], acc[nt][3]));
        }
        mx0 = fmaxf(mx0, __shfl_xor_sync(0xffffffffu, mx0, 1));
        mx0 = fmaxf(mx0, __shfl_xor_sync(0xffffffffu, mx0, 2));
        mx1 = fmaxf(mx1, __shfl_xor_sync(0xffffffffu, mx1, 1));
        mx1 = fmaxf(mx1, __shfl_xor_sync(0xffffffffu, mx1, 2));

        float mn0 = fmaxf(m_[0], mx0), mn1 = fmaxf(m_[1], mx1);
        float al0 = __expf(m_[0] - mn0), al1 = __expf(m_[1] - mn1);
        m_[0] = mn0; m_[1] = mn1;

        float rs0 = 0.0f, rs1 = 0.0f;
#pragma unroll
        for (int nt = 0; nt < 8; nt++) {
            acc[nt][0] = __expf(acc[nt][0] - mn0); rs0 += acc[nt][0];
            acc[nt][1] = __expf(acc[nt][1] - mn0); rs0 += acc[nt][1];
            acc[nt][2] = __expf(acc[nt][2] - mn1); rs1 += acc[nt][2];
            acc[nt][3] = __expf(acc[nt][3] - mn1); rs1 += acc[nt][3];
        }
        rs0 += __shfl_xor_sync(0xffffffffu, rs0, 1);
        rs0 += __shfl_xor_sync(0xffffffffu, rs0, 2);
        rs1 += __shfl_xor_sync(0xffffffffu, rs1, 1);
        rs1 += __shfl_xor_sync(0xffffffffu, rs1, 2);

        l_[0] = l_[0] * al0 + rs0;
        l_[1] = l_[1] * al1 + rs1;
#pragma unroll
        for (int n = 0; n < 16; n++) {
            o_[n][0] *= al0; o_[n][1] *= al0;
            o_[n][2] *= al1; o_[n][3] *= al1;
        }

        {
            int pb = w * 512;
#pragma unroll
            for (int nt = 0; nt < 8; nt++) {
                int a0 = pb + ((nt >> 1) * 32 + lane) * 4 + 2 * (nt & 1);
                Ps[a0]     = f22h2(acc[nt][0], acc[nt][1]);
                Ps[a0 + 1] = f22h2(acc[nt][2], acc[nt][3]);
            }
        }
        __syncwarp();

        {
            int pb = w * 512;
#pragma unroll
            for (int ks = 0; ks < 4; ks++) {
                uint4 a = *(const uint4*)&Ps[pb + (ks * 32 + lane) * 4];
#pragma unroll
                for (int nt = 0; nt < 16; nt++) {
                    uint2 b = *(const uint2*)&Vs[((ks * 16 + nt) * 32 + lane) * 2];
                    mma_f16(o_[nt][0], o_[nt][1], o_[nt][2], o_[nt][3],
                            a.x, a.y, a.z, a.w, b.x, b.y);
                }
            }
        }
        __syncthreads();
    }

    float inv0 = 1.0f / l_[0], inv1 = 1.0f / l_[1];
#pragma unroll
    for (int nt = 0; nt < 16; nt++) {
        int col = h * D_HEAD + nt * 8 + c2;
        *(uint32_t*)&O[(size_t)rg0 * QCOLS + col] =
            f22h2(o_[nt][0] * inv0, o_[nt][1] * inv0);
        *(uint32_t*)&O[(size_t)rg1 * QCOLS + col] =
            f22h2(o_[nt][2] * inv1, o_[nt][3] * inv1);
    }
}

// ============================================================================
// kernel_launch
// inputs: 0 hidden f32, 1 mask (unused), 2 pos i32, 3 Wq, 4 Wk, 5 Wv, 6 Wo
// ============================================================================
extern "C" void kernel_launch(void* const* d_in, const int* in_sizes, int n_in,
                              void* d_out, int out_size) {
    (void)in_sizes; (void)n_in; (void)out_size;
    const float* hidden = (const float*)d_in[0];
    const int*   pos    = (const int*)d_in[2];
    const float* Wq     = (const float*)d_in[3];
    const float* Wk     = (const float*)d_in[4];
    const float* Wv     = (const float*)d_in[5];
    const float* Wo     = (const float*)d_in[6];
    float* out = (float*)d_out;

    __half *Qp, *Kp, *Vp, *Ap;
    cudaGetSymbolAddress((void**)&Qp, g_Q);
    cudaGetSymbolAddress((void**)&Kp, g_K);
    cudaGetSymbolAddress((void**)&Vp, g_V);
    cudaGetSymbolAddress((void**)&Ap, g_A);

    cudaFuncSetAttribute(flash_f16,
                         cudaFuncAttributeMaxDynamicSharedMemorySize, SMEM_FAH);

    const float SCALE = 0.08838834764831845f;   // 1/sqrt(128)
    dim3 blk(256);
    // fused QKV projection: 20 n-tiles x 24 m-tiles
    qkv_gemm<<<dim3((QCOLS + 2 * KCOLS) / 128, S_LEN / 128), blk>>>(hidden, Wq, Wk, Wv);
    // RoPE (Q also gets the softmax scale folded in)
    rope_half<<<(S_LEN * HQ * 64 + 255) / 256, 256>>>(Qp, pos, HQ, S_LEN * HQ * 64, SCALE);
    rope_half<<<(S_LEN * HK * 64 + 255) / 256, 256>>>(Kp, pos, HK, S_LEN * HK * 64, 1.0f);
    // fp16 causal flash attention: 24 q-tiles x 16 heads
    flash_f16<<<dim3(S_LEN / 128, HQ), blk, SMEM_FAH>>>(Qp, Kp, Vp, Ap);
    // output projection
    wo_gemm<<<dim3(QCOLS / 128, S_LEN / 128), blk>>>(Ap, Wo, out, S_LEN, QCOLS, HIDDEN);
}